// round 8
// baseline (speedup 1.0000x reference)
#include <cuda_runtime.h>
#include <cuda_bf16.h>
#include <math.h>

#define BB 4
#define CIN 3
#define CC 32
#define HH 256
#define WW 256
#define MM 16
#define NB 4
#define OC 4
#define PIX (HH*WW)
#define GSTR 260
#define HSTR 258

typedef unsigned long long ull;

__device__ __forceinline__ ull pk2(float lo, float hi) {
    ull r; asm("mov.b64 %0,{%1,%2};" : "=l"(r) : "f"(lo), "f"(hi)); return r;
}
__device__ __forceinline__ void up2(ull v, float& a, float& b) {
    asm("mov.b64 {%0,%1},%2;" : "=f"(a), "=f"(b) : "l"(v));
}
__device__ __forceinline__ ull fma2(ull a, ull b, ull c) {
    ull d; asm("fma.rn.f32x2 %0,%1,%2,%3;" : "=l"(d) : "l"(a), "l"(b), "l"(c)); return d;
}
__device__ __forceinline__ ull mul2(ull a, ull b) {
    ull d; asm("mul.rn.f32x2 %0,%1,%2;" : "=l"(d) : "l"(a), "l"(b)); return d;
}
__device__ __forceinline__ ull add2(ull a, ull b) {
    ull d; asm("add.rn.f32x2 %0,%1,%2;" : "=l"(d) : "l"(a), "l"(b)); return d;
}
__device__ __forceinline__ ull neg2(ull a) { return a ^ 0x8000000080000000ULL; }

__device__ __forceinline__ float gelu1(float v) {
    return 0.5f * v * (1.f + erff(v * 0.70710678118654752f));
}

// Scratch (device globals: allocation-free)
__device__ float  g_x0[BB*CC*PIX];
__device__ float  g_xa[OC*BB*CC*PIX];
__device__ float  g_xb[OC*BB*CC*PIX];
__device__ float2 g_S [OC*BB*MM*HH*CC];            // [boh][m][h][c]
__device__ float2 g_X [OC*BB*CC*MM*MM];
__device__ float2 g_X0[BB*CC*MM*MM];
__device__ float2 g_Y [OC*BB*CC*MM*MM];
__device__ float2 g_W [OC*NB*MM*MM*CC*CC];         // [ohn][kl][c][o]
__device__ float2 g_tw2[256];

__global__ void init_tw() {
    int t = threadIdx.x;
    double a = 6.283185307179586476925286766559 * (double)t / 256.0;
    g_tw2[t] = make_float2((float)cos(a), (float)sin(a));
}

__global__ void init_w(const float* __restrict__ wr, const float* __restrict__ wi) {
    long d = (long)blockIdx.x * blockDim.x + threadIdx.x;
    int o   = (int)(d & 31);
    int c   = (int)((d >> 5) & 31);
    int kl  = (int)((d >> 10) & 255);
    int ohn = (int)(d >> 18);
    int k = kl >> 4, l = kl & 15;
    long s = ((((long)ohn * 32 + c) * 32 + o) * 16 + k) * 16 + l;
    g_W[d] = make_float2(wr[s], wi[s]);
}

__global__ void klift(const float* __restrict__ x, const float* __restrict__ lw,
                      const float* __restrict__ lb) {
    int idx = blockIdx.x * 256 + threadIdx.x;
    int pix = idx & (PIX - 1);
    int bc  = idx >> 16;
    int c = bc & 31, b = bc >> 5;
    float acc = lb[c];
    #pragma unroll
    for (int i = 0; i < CIN; i++)
        acc = fmaf(x[(b * CIN + i) * PIX + pix], lw[c * CIN + i], acc);
    g_x0[idx] = acc;
}

// K1 (once): packed W-axis truncated DFT of x0 -> S[b][m][h][c]
__global__ void k1(const float* __restrict__ xin) {
    __shared__ __align__(16) float xs[32 * GSTR];
    __shared__ float2 tws[256];
    int row0 = blockIdx.x * 32;
    for (int i = threadIdx.x; i < 8192; i += 256)
        xs[(i >> 8) * GSTR + (i & 255)] = xin[(long)row0 * 256 + i];
    tws[threadIdx.x] = g_tw2[threadIdx.x];
    __syncthreads();
    int b = row0 >> 13, c = (row0 >> 8) & 31, h0 = row0 & 255;
    int m = threadIdx.x >> 4, hh = threadIdx.x & 15;
    float sgn = (m & 1) ? -1.f : 1.f;
    ull sgn2 = pk2(sgn, sgn);
    float2 tm = tws[m], st = tws[(2 * m) & 255];
    ull cs = pk2(st.x, st.x), ss = pk2(st.y, st.y), nss = neg2(ss);
    ull c0 = pk2(1.f, tm.x), s0 = pk2(0.f, tm.y);
    ull arA = 0, asA = 0, arB = 0, asB = 0;
    const float* xr0 = xs + hh * GSTR;
    const float* xr1 = xs + (hh + 16) * GSTR;
    #pragma unroll 4
    for (int w = 0; w < 128; w += 2) {
        ull A0 = *(const ull*)(xr0 + w), B0 = *(const ull*)(xr0 + w + 128);
        ull A1 = *(const ull*)(xr1 + w), B1 = *(const ull*)(xr1 + w + 128);
        ull u0 = fma2(sgn2, B0, A0), u1 = fma2(sgn2, B1, A1);
        arA = fma2(u0, c0, arA); asA = fma2(u0, s0, asA);
        arB = fma2(u1, c0, arB); asB = fma2(u1, s0, asB);
        ull cn = fma2(c0, cs, mul2(s0, nss));
        s0 = fma2(s0, cs, mul2(c0, ss)); c0 = cn;
    }
    float a, q;
    up2(arA, a, q); float ar = a + q; up2(asA, a, q); float ai = -(a + q);
    g_S[(((long)(b * 16 + m) * 256) + h0 + hh) * 32 + c] = make_float2(ar, ai);
    up2(arB, a, q); ar = a + q; up2(asB, a, q); ai = -(a + q);
    g_S[(((long)(b * 16 + m) * 256) + h0 + hh + 16) * 32 + c] = make_float2(ar, ai);
}

// K2a: packed H-axis truncated DFT (+1/256). grid(16 l, ng, 2 chalf), 256 thr.
__global__ void k2a(const float2* __restrict__ S, float2* __restrict__ X) {
    __shared__ __align__(16) float Sre[16 * HSTR];
    __shared__ __align__(16) float Sim[16 * HSTR];
    __shared__ float2 tws[256];
    int l = blockIdx.x, g = blockIdx.y, ch = blockIdx.z;
    const float2* Sp = S + ((long)(g * 16 + l) * 256) * 32 + ch * 16;
    for (int i = threadIdx.x; i < 4096; i += 256) {
        int hh = i >> 4, cc = i & 15;
        float2 v = Sp[hh * 32 + cc];
        Sre[cc * HSTR + hh] = v.x; Sim[cc * HSTR + hh] = v.y;
    }
    tws[threadIdx.x] = g_tw2[threadIdx.x];
    __syncthreads();
    int c16 = threadIdx.x & 15, k = threadIdx.x >> 4;
    float sgn = (k & 1) ? -1.f : 1.f;
    ull sgn2 = pk2(sgn, sgn);
    float2 tk = tws[k], st = tws[(2 * k) & 255];
    ull cs = pk2(st.x, st.x), ss = pk2(st.y, st.y), nss = neg2(ss);
    ull c0 = pk2(1.f, tk.x), s0 = pk2(0.f, tk.y);
    ull arA = 0, arB = 0, aiA = 0, aiB = 0;
    const float* re = Sre + c16 * HSTR;
    const float* im = Sim + c16 * HSTR;
    #pragma unroll 4
    for (int hq = 0; hq < 128; hq += 2) {
        ull rA = *(const ull*)(re + hq), rB = *(const ull*)(re + hq + 128);
        ull iA = *(const ull*)(im + hq), iB = *(const ull*)(im + hq + 128);
        ull ux = fma2(sgn2, rB, rA), uy = fma2(sgn2, iB, iA);
        arA = fma2(ux, c0, arA); arB = fma2(uy, s0, arB);
        aiA = fma2(uy, c0, aiA); aiB = fma2(ux, s0, aiB);
        ull cn = fma2(c0, cs, mul2(s0, nss));
        s0 = fma2(s0, cs, mul2(c0, ss)); c0 = cn;
    }
    float a, q;
    up2(arA, a, q); float ar = a + q; up2(arB, a, q); ar += a + q;
    up2(aiA, a, q); float ai = a + q; up2(aiB, a, q); ai -= a + q;
    X[((long)(g * 32 + ch * 16 + c16)) * 256 + k * 16 + l] =
        make_float2(ar * (1.f / 256.f), ai * (1.f / 256.f));
}

// K2b: channel mix. grid(256 kl, OC oh), 128 thr.
__global__ void k2b(const float2* __restrict__ X, int x_oh_mult, int n) {
    __shared__ float2 Ws[32 * 32];
    __shared__ float2 Xs[4][32];
    int kl = blockIdx.x, oh = blockIdx.y;
    const float2* Wt = g_W + ((long)(oh * NB + n) * 256 + kl) * 1024;
    for (int i = threadIdx.x; i < 1024; i += 128) Ws[i] = Wt[i];
    {
        int b = threadIdx.x >> 5, c = threadIdx.x & 31;
        Xs[b][c] = X[((long)((oh * x_oh_mult + b) * 32 + c)) * 256 + kl];
    }
    __syncthreads();
    int b = threadIdx.x >> 5, o = threadIdx.x & 31;
    float yr = 0.f, yi = 0.f;
    #pragma unroll
    for (int c0 = 0; c0 < 32; c0++) {
        float2 xv = Xs[b][c0];
        float2 wv = Ws[c0 * 32 + o];
        yr += xv.x * wv.x - xv.y * wv.y;
        yi += xv.x * wv.y + xv.y * wv.x;
    }
    g_Y[((long)((oh * 4 + b) * 32 + o)) * 256 + kl] = make_float2(yr, yi);
}

// K3: H-inverse + half-spectrum W-inverse + packed bypass + GELU,
// then (LAST ? projection : next-iteration packed W-DFT with 2o x 2m tiling)
template <bool LAST>
__global__ void __launch_bounds__(256, 2) k3(
    const float* __restrict__ xin, int in_nb, float* __restrict__ xout,
    const float* __restrict__ byp_w, const float* __restrict__ byp_b,
    const float* __restrict__ pw, const float* __restrict__ pb, int n) {
    __shared__ __align__(16) float gs[32 * GSTR];      // 33280B
    __shared__ __align__(16) ulonglong2 Bs2[32 * 16];  // 8192B (Br2, -Bi2), reused as red[]
    __shared__ __align__(16) ull bwT2[32 * 32];        // [i][o] replicated packs, 8192B
    __shared__ float2 tws[256];
    __shared__ float pws[32];
    int h = blockIdx.x, boh = blockIdx.y;
    int b = boh & 3, oh = boh >> 2;
    int ohn = oh * NB + n;
    int t = threadIdx.x;

    tws[t] = g_tw2[t];
    {   // bypass weights [o][i] -> [i][o], replicated f32x2 packs
        const float* bwp = byp_w + ohn * 1024;
        #pragma unroll
        for (int r = 0; r < 4; r++) {
            int idx = t + r * 256;
            float v = bwp[idx];
            bwT2[(idx & 31) * 32 + (idx >> 5)] = pk2(v, v);
        }
    }
    if (LAST && t < 32) pws[t] = pw[t];
    __syncthreads();

    // Phase B: H-inverse of Y; store scaled, imag-negated, replicated
    {
        const float* bbp = byp_b + ohn * 32;
        const float2* Yb = g_Y + (long)boh * 8192;
        #pragma unroll
        for (int rep = 0; rep < 2; rep++) {
            int idx = t + rep * 256;
            int o = idx >> 4, l = idx & 15;
            float br = 0.f, bi = 0.f;
            #pragma unroll
            for (int k = 0; k < 16; k++) {
                float2 y = Yb[o * 256 + k * 16 + l];
                float2 tw = tws[(k * h) & 255];
                br += y.x * tw.x - y.y * tw.y;
                bi += y.x * tw.y + y.y * tw.x;
            }
            float sc = (l == 0) ? (1.f / 256.f) : (2.f / 256.f);
            br *= sc; bi *= -sc;
            if (l == 0) br += bbp[o];          // fold bias; DC imag dropped (C2R)
            Bs2[idx] = make_ulonglong2(pk2(br, br), pk2(bi, bi));
        }
    }
    __syncthreads();

    // Phase C: thread = (og, wg): 4 o x 8 w via half-spectrum fold.
    // E = DC + even-l terms, O = odd-l terms; spec(w)=E+O, spec(w+128)=E-O.
    {
        int wg = t & 31, og = t >> 5;
        int w0 = wg * 4, o0 = og * 4;
        float2 t0 = tws[w0], t1 = tws[w0 + 1], t2 = tws[w0 + 2], t3 = tws[w0 + 3];
        ull stcA = pk2(t0.x, t1.x), stsA = pk2(t0.y, t1.y);
        ull stcB = pk2(t2.x, t3.x), stsB = pk2(t2.y, t3.y);
        ull nstsA = neg2(stsA), nstsB = neg2(stsB);
        ull cA = stcA, sA = stsA, cB = stcB, sB = stsB;
        ull E[8], O[8];                     // [oo*2 + pack]
        #pragma unroll
        for (int oo = 0; oo < 4; oo++) {
            ull dc = Bs2[(o0 + oo) * 16].x;
            E[oo * 2] = dc; E[oo * 2 + 1] = dc;
            O[oo * 2] = 0;  O[oo * 2 + 1] = 0;
        }
        #pragma unroll
        for (int l = 1; l < 16; l++) {
            #pragma unroll
            for (int oo = 0; oo < 4; oo++) {
                ulonglong2 Bv = Bs2[(o0 + oo) * 16 + l];
                if (l & 1) {
                    O[oo * 2]     = fma2(Bv.x, cA, O[oo * 2]);
                    O[oo * 2]     = fma2(Bv.y, sA, O[oo * 2]);
                    O[oo * 2 + 1] = fma2(Bv.x, cB, O[oo * 2 + 1]);
                    O[oo * 2 + 1] = fma2(Bv.y, sB, O[oo * 2 + 1]);
                } else {
                    E[oo * 2]     = fma2(Bv.x, cA, E[oo * 2]);
                    E[oo * 2]     = fma2(Bv.y, sA, E[oo * 2]);
                    E[oo * 2 + 1] = fma2(Bv.x, cB, E[oo * 2 + 1]);
                    E[oo * 2 + 1] = fma2(Bv.y, sB, E[oo * 2 + 1]);
                }
            }
            if (l < 15) {
                ull cn = fma2(cA, stcA, mul2(sA, nstsA));
                sA = fma2(sA, stcA, mul2(cA, stsA)); cA = cn;
                cn = fma2(cB, stcB, mul2(sB, nstsB));
                sB = fma2(sB, stcB, mul2(cB, stsB)); cB = cn;
            }
        }
        // combine: sp[oo*4 + {0,1}] = lo (w0..w0+3), {2,3} = hi (+128)
        ull sp[16];
        #pragma unroll
        for (int oo = 0; oo < 4; oo++) {
            sp[oo * 4 + 0] = add2(E[oo * 2],     O[oo * 2]);
            sp[oo * 4 + 1] = add2(E[oo * 2 + 1], O[oo * 2 + 1]);
            sp[oo * 4 + 2] = add2(E[oo * 2],     neg2(O[oo * 2]));
            sp[oo * 4 + 3] = add2(E[oo * 2 + 1], neg2(O[oo * 2 + 1]));
        }
        // bypass conv
        int inb = (in_nb == 4) ? b : boh;
        const float* xrow = xin + (((long)inb * 32) << 16) + (h << 8) + w0;
        #pragma unroll 4
        for (int i = 0; i < 32; i++) {
            float4 xa4 = *(const float4*)(xrow + ((long)i << 16));
            float4 xb4 = *(const float4*)(xrow + ((long)i << 16) + 128);
            ull xA0 = pk2(xa4.x, xa4.y), xA1 = pk2(xa4.z, xa4.w);
            ull xB0 = pk2(xb4.x, xb4.y), xB1 = pk2(xb4.z, xb4.w);
            const ulonglong2* wp = (const ulonglong2*)(bwT2 + i * 32 + o0);
            ulonglong2 wq0 = wp[0], wq1 = wp[1];
            sp[0]  = fma2(wq0.x, xA0, sp[0]);  sp[1]  = fma2(wq0.x, xA1, sp[1]);
            sp[2]  = fma2(wq0.x, xB0, sp[2]);  sp[3]  = fma2(wq0.x, xB1, sp[3]);
            sp[4]  = fma2(wq0.y, xA0, sp[4]);  sp[5]  = fma2(wq0.y, xA1, sp[5]);
            sp[6]  = fma2(wq0.y, xB0, sp[6]);  sp[7]  = fma2(wq0.y, xB1, sp[7]);
            sp[8]  = fma2(wq1.x, xA0, sp[8]);  sp[9]  = fma2(wq1.x, xA1, sp[9]);
            sp[10] = fma2(wq1.x, xB0, sp[10]); sp[11] = fma2(wq1.x, xB1, sp[11]);
            sp[12] = fma2(wq1.y, xA0, sp[12]); sp[13] = fma2(wq1.y, xA1, sp[13]);
            sp[14] = fma2(wq1.y, xB0, sp[14]); sp[15] = fma2(wq1.y, xB1, sp[15]);
        }
        // GELU + stores
        #pragma unroll
        for (int oo = 0; oo < 4; oo++) {
            int o = o0 + oo;
            float v0, v1, v2, v3;
            up2(sp[oo * 4 + 0], v0, v1); up2(sp[oo * 4 + 1], v2, v3);
            float4 glo = make_float4(gelu1(v0), gelu1(v1), gelu1(v2), gelu1(v3));
            up2(sp[oo * 4 + 2], v0, v1); up2(sp[oo * 4 + 3], v2, v3);
            float4 ghi = make_float4(gelu1(v0), gelu1(v1), gelu1(v2), gelu1(v3));
            *(float4*)(gs + o * GSTR + w0)       = glo;
            *(float4*)(gs + o * GSTR + w0 + 128) = ghi;
            if (!LAST) {
                float* orow = xout + (((long)(boh * 32 + o)) << 16) + (h << 8) + w0;
                *(float4*)orow         = glo;
                *(float4*)(orow + 128) = ghi;
            }
        }
    }
    __syncthreads();

    if (!LAST) {
        // Phase D: next-iteration W-DFT, 2o x 2m per thread, w split across halves
        int wbase = (t >> 7) << 6;          // 0 or 64
        int tl = t & 127;
        int op = tl & 15, mp = tl >> 4;
        int m0 = mp, m1 = mp + 8;
        float sgn = (mp & 1) ? -1.f : 1.f;  // m0, m1 share parity
        ull sgn2 = pk2(sgn, sgn);
        ull c0 = pk2(tws[(m0 * wbase) & 255].x, tws[(m0 * (wbase + 1)) & 255].x);
        ull s0 = pk2(tws[(m0 * wbase) & 255].y, tws[(m0 * (wbase + 1)) & 255].y);
        ull c1 = pk2(tws[(m1 * wbase) & 255].x, tws[(m1 * (wbase + 1)) & 255].x);
        ull s1 = pk2(tws[(m1 * wbase) & 255].y, tws[(m1 * (wbase + 1)) & 255].y);
        float2 st0 = tws[(2 * m0) & 255], st1 = tws[(2 * m1) & 255];
        ull cs0 = pk2(st0.x, st0.x), ss0 = pk2(st0.y, st0.y), nss0 = neg2(ss0);
        ull cs1 = pk2(st1.x, st1.x), ss1 = pk2(st1.y, st1.y), nss1 = neg2(ss1);
        const float* go0 = gs + op * GSTR;
        const float* go1 = gs + (op + 16) * GSTR;
        ull r00 = 0, i00 = 0, r01 = 0, i01 = 0, r10 = 0, i10 = 0, r11 = 0, i11 = 0;
        #pragma unroll 4
        for (int w = wbase; w < wbase + 64; w += 2) {
            ull A0 = *(const ull*)(go0 + w), B0 = *(const ull*)(go0 + w + 128);
            ull A1 = *(const ull*)(go1 + w), B1 = *(const ull*)(go1 + w + 128);
            ull u0 = fma2(sgn2, B0, A0), u1 = fma2(sgn2, B1, A1);
            r00 = fma2(u0, c0, r00); i00 = fma2(u0, s0, i00);
            r01 = fma2(u1, c0, r01); i01 = fma2(u1, s0, i01);
            r10 = fma2(u0, c1, r10); i10 = fma2(u0, s1, i10);
            r11 = fma2(u1, c1, r11); i11 = fma2(u1, s1, i11);
            ull cn = fma2(c0, cs0, mul2(s0, nss0));
            s0 = fma2(s0, cs0, mul2(c0, ss0)); c0 = cn;
            cn = fma2(c1, cs1, mul2(s1, nss1));
            s1 = fma2(s1, cs1, mul2(c1, ss1)); c1 = cn;
        }
        // cross-half reduction via smem (reuse Bs2 storage)
        ull* red = (ull*)Bs2;
        if (t >= 128) {
            ull* rp = red + tl * 8;
            rp[0] = r00; rp[1] = i00; rp[2] = r01; rp[3] = i01;
            rp[4] = r10; rp[5] = i10; rp[6] = r11; rp[7] = i11;
        }
        __syncthreads();
        if (t < 128) {
            const ull* rp = red + tl * 8;
            r00 = add2(r00, rp[0]); i00 = add2(i00, rp[1]);
            r01 = add2(r01, rp[2]); i01 = add2(i01, rp[3]);
            r10 = add2(r10, rp[4]); i10 = add2(i10, rp[5]);
            r11 = add2(r11, rp[6]); i11 = add2(i11, rp[7]);
            float a, q, re, im;
            up2(r00, a, q); re = a + q; up2(i00, a, q); im = -(a + q);
            g_S[(((long)(boh * 16 + m0) * 256) + h) * 32 + op]      = make_float2(re, im);
            up2(r01, a, q); re = a + q; up2(i01, a, q); im = -(a + q);
            g_S[(((long)(boh * 16 + m0) * 256) + h) * 32 + op + 16] = make_float2(re, im);
            up2(r10, a, q); re = a + q; up2(i10, a, q); im = -(a + q);
            g_S[(((long)(boh * 16 + m1) * 256) + h) * 32 + op]      = make_float2(re, im);
            up2(r11, a, q); re = a + q; up2(i11, a, q); im = -(a + q);
            g_S[(((long)(boh * 16 + m1) * 256) + h) * 32 + op + 16] = make_float2(re, im);
        }
    } else {
        // projection
        float pacc = 0.f;
        #pragma unroll
        for (int o = 0; o < 32; o++)
            pacc = fmaf(gs[o * GSTR + t], pws[o], pacc);
        xout[(((long)(b * OC + oh) * 256 + h) << 8) + t] = pacc + pb[0];
    }
}

extern "C" void kernel_launch(void* const* d_in, const int* in_sizes, int n_in,
                              void* d_out, int out_size) {
    const float* x      = (const float*)d_in[0];
    const float* lift_w = (const float*)d_in[1];
    const float* lift_b = (const float*)d_in[2];
    const float* wr     = (const float*)d_in[3];
    const float* wi     = (const float*)d_in[4];
    const float* byp_w  = (const float*)d_in[5];
    const float* byp_b  = (const float*)d_in[6];
    const float* proj_w = (const float*)d_in[7];
    const float* proj_b = (const float*)d_in[8];
    float* out = (float*)d_out;

    float *x0, *xa, *xb;
    float2 *S, *X, *X0;
    cudaGetSymbolAddress((void**)&x0, g_x0);
    cudaGetSymbolAddress((void**)&xa, g_xa);
    cudaGetSymbolAddress((void**)&xb, g_xb);
    cudaGetSymbolAddress((void**)&S,  g_S);
    cudaGetSymbolAddress((void**)&X,  g_X);
    cudaGetSymbolAddress((void**)&X0, g_X0);

    init_tw<<<1, 256>>>();
    init_w<<<4096, 1024>>>(wr, wi);
    klift<<<(BB * CC * PIX) / 256, 256>>>(x, lift_w, lift_b);
    k1<<<1024, 256>>>(x0);                          // S(x0)
    k2a<<<dim3(16, 4, 2), 256>>>(S, X0);            // X(x0), shared across oh

    dim3 g3(256, 16);
    // n = 0 (all oh concurrent)
    k2b<<<dim3(256, OC), 128>>>(X0, 0, 0);
    k3<false><<<g3, 256>>>(x0, 4, xa, byp_w, byp_b, proj_w, proj_b, 0);
    // n = 1
    k2a<<<dim3(16, 16, 2), 256>>>(S, X);
    k2b<<<dim3(256, OC), 128>>>(X, 4, 1);
    k3<false><<<g3, 256>>>(xa, 16, xb, byp_w, byp_b, proj_w, proj_b, 1);
    // n = 2
    k2a<<<dim3(16, 16, 2), 256>>>(S, X);
    k2b<<<dim3(256, OC), 128>>>(X, 4, 2);
    k3<false><<<g3, 256>>>(xb, 16, xa, byp_w, byp_b, proj_w, proj_b, 2);
    // n = 3 (fused projection)
    k2a<<<dim3(16, 16, 2), 256>>>(S, X);
    k2b<<<dim3(256, OC), 128>>>(X, 4, 3);
    k3<true><<<g3, 256>>>(xa, 16, out, byp_w, byp_b, proj_w, proj_b, 3);
}